// round 1
// baseline (speedup 1.0000x reference)
#include <cuda_runtime.h>
#include <cstdint>

// PWC-Net correlation: out[b, (dy*9+dx), h, w] = (1/C) * sum_c first[b,c,h,w] * second_pad[b,c,h+dy-4,w+dx-4]
// Shapes fixed by the problem: B=8, C=128, H=112, W=192, 81 displacement channels.

#define B_ 8
#define C_ 128
#define H_ 112
#define W_ 192
#define HW_ (H_ * W_)

typedef unsigned long long ull;

// packed f32x2 FMA: acc.lo += a.lo*b.lo; acc.hi += a.hi*b.hi
__device__ __forceinline__ void fma2(ull& acc, ull a, ull b) {
    asm("fma.rn.f32x2 %0, %1, %2, %0;" : "+l"(acc) : "l"(a), "l"(b));
}
__device__ __forceinline__ void mul2(ull& v, ull s) {
    asm("mul.rn.f32x2 %0, %0, %1;" : "+l"(v) : "l"(s));
}
// new pair = (hi of a, lo of b)
__device__ __forceinline__ ull pack_hl(ull a, ull b) {
    return (a >> 32) | (b << 32);
}

__global__ __launch_bounds__(96, 3)
void corr81_kernel(const float* __restrict__ first,
                   const float* __restrict__ second,
                   float* __restrict__ out) {
    const int h   = blockIdx.x;   // 0..111
    const int b   = blockIdx.y;   // 0..7
    const int tid = threadIdx.x;  // 0..95
    const int w0  = 2 * tid;      // even pixel base; thread owns pixels w0, w0+1

    // 81 packed accumulators: lane0 = pixel w0, lane1 = pixel w0+1
    ull acc[81];
#pragma unroll
    for (int i = 0; i < 81; i++) acc[i] = 0ull;

    // interior: needs second columns [w0-4, w0+5] all in [0, W)
    const bool interior = (w0 >= 4) && (w0 + 5 < W_);

    const float* fbase = first  + ((size_t)(b * C_) * H_ + h) * W_ + w0;
    const float* sbase = second + ((size_t)(b * C_) * H_) * W_;

    for (int c = 0; c < C_; c++) {
        const ull f2 = *reinterpret_cast<const ull*>(fbase + (size_t)c * HW_);
        const float* schan = sbase + (size_t)c * HW_;

#pragma unroll
        for (int dy = 0; dy < 9; dy++) {
            const int y = h + dy - 4;
            if (y < 0 || y >= H_) continue;   // warp-uniform (depends on blockIdx only)
            const float* srow = schan + y * W_;

            ull p[9];
            if (interior) {
                // five aligned 64-bit loads cover columns w0-4 .. w0+5
                const ull v0 = *reinterpret_cast<const ull*>(srow + w0 - 4);
                const ull v1 = *reinterpret_cast<const ull*>(srow + w0 - 2);
                const ull v2 = *reinterpret_cast<const ull*>(srow + w0);
                const ull v3 = *reinterpret_cast<const ull*>(srow + w0 + 2);
                const ull v4 = *reinterpret_cast<const ull*>(srow + w0 + 4);
                p[0] = v0; p[2] = v1; p[4] = v2; p[6] = v3; p[8] = v4;
                p[1] = pack_hl(v0, v1);
                p[3] = pack_hl(v1, v2);
                p[5] = pack_hl(v2, v3);
                p[7] = pack_hl(v3, v4);
            } else {
                float s[10];
#pragma unroll
                for (int j = 0; j < 10; j++) {
                    const int x = w0 - 4 + j;
                    s[j] = (x >= 0 && x < W_) ? srow[x] : 0.0f;
                }
#pragma unroll
                for (int dx = 0; dx < 9; dx++)
                    p[dx] = (ull)__float_as_uint(s[dx]) |
                            ((ull)__float_as_uint(s[dx + 1]) << 32);
            }

#pragma unroll
            for (int dx = 0; dx < 9; dx++)
                fma2(acc[dy * 9 + dx], f2, p[dx]);
        }
    }

    // scale by 1/C and store packed pairs (8B aligned: w0 even)
    const float inv_c = 1.0f / (float)C_;
    const unsigned sb = __float_as_uint(inv_c);
    const ull scale2 = (ull)sb | ((ull)sb << 32);

    float* obase = out + (((size_t)b * 81) * H_ + h) * W_ + w0;
#pragma unroll
    for (int d = 0; d < 81; d++) {
        mul2(acc[d], scale2);
        *reinterpret_cast<ull*>(obase + (size_t)d * HW_) = acc[d];
    }
}

extern "C" void kernel_launch(void* const* d_in, const int* in_sizes, int n_in,
                              void* d_out, int out_size) {
    const float* first  = (const float*)d_in[0];
    const float* second = (const float*)d_in[1];
    float* out = (float*)d_out;

    dim3 grid(H_, B_);   // (112, 8)
    dim3 block(96);
    corr81_kernel<<<grid, block>>>(first, second, out);
}

// round 2
// speedup vs baseline: 2.2550x; 2.2550x over previous
#include <cuda_runtime.h>
#include <cstdint>

// PWC-Net correlation: out[b, (dy*9+dx), h, w] = (1/C) * sum_c first[b,c,h,w] * second_pad[b,c,h+dy-4,w+dx-4]
// B=8, C=128, H=112, W=192, 81 displacement channels.
//
// Round 2: split the 81 displacements into 3 dy-groups of 27 per thread
// (54 acc regs instead of 162) so ptxas can front-batch loads (MLP ~15)
// and occupancy rises. dy groups read disjoint rows -> no traffic increase.

#define B_ 8
#define C_ 128
#define H_ 112
#define W_ 192
#define HW_ (H_ * W_)

typedef unsigned long long ull;

__device__ __forceinline__ void fma2(ull& acc, ull a, ull b) {
    asm("fma.rn.f32x2 %0, %1, %2, %0;" : "+l"(acc) : "l"(a), "l"(b));
}
__device__ __forceinline__ void mul2(ull& v, ull s) {
    asm("mul.rn.f32x2 %0, %0, %1;" : "+l"(v) : "l"(s));
}
// new pair = (hi of a, lo of b)
__device__ __forceinline__ ull pack_hl(ull a, ull b) {
    return (a >> 32) | (b << 32);
}

__global__ __launch_bounds__(288, 2)
void corr81_kernel(const float* __restrict__ first,
                   const float* __restrict__ second,
                   float* __restrict__ out) {
    const int h   = blockIdx.x;        // 0..111
    const int b   = blockIdx.y;        // 0..7
    const int tid = threadIdx.x;       // 0..287
    const int pp  = tid % 96;          // pixel-pair index
    const int g   = tid / 96;          // dy group 0..2 (dy = g*3 + i)
    const int w0  = 2 * pp;

    ull acc[27];
#pragma unroll
    for (int i = 0; i < 27; i++) acc[i] = 0ull;

    const bool interior = (w0 >= 4) && (w0 + 5 < W_);

    const float* fbase = first  + ((size_t)(b * C_) * H_ + h) * W_ + w0;
    const float* sbase = second + (size_t)(b * C_) * HW_;
    const int y0 = h + g * 3 - 4;

    for (int c = 0; c < C_; c++) {
        const ull f2 = *reinterpret_cast<const ull*>(fbase + (size_t)c * HW_);
        const float* schan = sbase + (size_t)c * HW_;

#pragma unroll
        for (int i = 0; i < 3; i++) {
            const int y = y0 + i;
            if (y < 0 || y >= H_) continue;   // warp-uniform (96 = 3 warps per group)
            const float* srow = schan + y * W_;

            ull p[9];
            if (interior) {
                const ull v0 = *reinterpret_cast<const ull*>(srow + w0 - 4);
                const ull v1 = *reinterpret_cast<const ull*>(srow + w0 - 2);
                const ull v2 = *reinterpret_cast<const ull*>(srow + w0);
                const ull v3 = *reinterpret_cast<const ull*>(srow + w0 + 2);
                const ull v4 = *reinterpret_cast<const ull*>(srow + w0 + 4);
                p[0] = v0; p[2] = v1; p[4] = v2; p[6] = v3; p[8] = v4;
                p[1] = pack_hl(v0, v1);
                p[3] = pack_hl(v1, v2);
                p[5] = pack_hl(v2, v3);
                p[7] = pack_hl(v3, v4);
            } else {
                float s[10];
#pragma unroll
                for (int j = 0; j < 10; j++) {
                    const int x = w0 - 4 + j;
                    s[j] = (x >= 0 && x < W_) ? srow[x] : 0.0f;
                }
#pragma unroll
                for (int dx = 0; dx < 9; dx++)
                    p[dx] = (ull)__float_as_uint(s[dx]) |
                            ((ull)__float_as_uint(s[dx + 1]) << 32);
            }

#pragma unroll
            for (int dx = 0; dx < 9; dx++)
                fma2(acc[i * 9 + dx], f2, p[dx]);
        }
    }

    const float inv_c = 1.0f / (float)C_;
    const unsigned sb = __float_as_uint(inv_c);
    const ull scale2 = (ull)sb | ((ull)sb << 32);

    // disp channel = (g*3 + i)*9 + dx  ->  base channel g*27, local d = i*9+dx
    float* obase = out + (((size_t)(b * 81 + g * 27)) * H_ + h) * W_ + w0;
#pragma unroll
    for (int d = 0; d < 27; d++) {
        mul2(acc[d], scale2);
        *reinterpret_cast<ull*>(obase + (size_t)d * HW_) = acc[d];
    }
}

extern "C" void kernel_launch(void* const* d_in, const int* in_sizes, int n_in,
                              void* d_out, int out_size) {
    const float* first  = (const float*)d_in[0];
    const float* second = (const float*)d_in[1];
    float* out = (float*)d_out;

    dim3 grid(H_, B_);   // (112, 8)
    dim3 block(288);     // 96 pixel-pairs x 3 dy-groups
    corr81_kernel<<<grid, block>>>(first, second, out);
}

// round 3
// speedup vs baseline: 5.1899x; 2.3015x over previous
#include <cuda_runtime.h>
#include <cstdint>

// PWC-Net correlation, B=8, C=128, H=112, W=192, 81 disps (dy,dx in [-4,4]).
// Round 3: (a) pre-padded second buffer -> no boundary code anywhere,
//          (b) swapped-operand FFMA2 for odd dx -> zero per-iter packing MOVs,
//          (c) immediate-offset loads from per-channel base pointers.

#define B_ 8
#define C_ 128
#define H_ 112
#define W_ 192
#define HW_ (H_ * W_)
#define HP_ 120     // H + 8
#define WP_ 200     // W + 8
#define HWP_ (HP_ * WP_)

typedef unsigned long long ull;

// zero-padded copy of `second`: [B, C, HP, WP], 98.3 MB
__device__ float g_second_pad[B_ * C_ * HWP_];

__device__ __forceinline__ void fma2(ull& acc, ull a, ull b) {
    asm("fma.rn.f32x2 %0, %1, %2, %0;" : "+l"(acc) : "l"(a), "l"(b));
}
__device__ __forceinline__ void mul2(ull& v, ull s) {
    asm("mul.rn.f32x2 %0, %0, %1;" : "+l"(v) : "l"(s));
}
__device__ __forceinline__ ull pack_hl(ull a, ull b) {   // (a.hi, b.lo)
    return (a >> 32) | (b << 32);
}
__device__ __forceinline__ ull swap2(ull a) {            // (a.hi, a.lo)
    return (a >> 32) | (a << 32);
}

__global__ __launch_bounds__(256)
void pad_kernel(const float* __restrict__ second) {
    int i = blockIdx.x * blockDim.x + threadIdx.x;       // float2 index
    const int total = B_ * C_ * HWP_ / 2;
    if (i >= total) return;
    int x2   = (i % (WP_ / 2)) * 2;                      // 0,2,..,198
    int rest = i / (WP_ / 2);
    int y    = rest % HP_;
    int bc   = rest / HP_;
    float2 v = make_float2(0.f, 0.f);
    int ys = y - 4;
    if (ys >= 0 && ys < H_) {
        const float* row = second + ((size_t)bc * H_ + ys) * W_;
        int x0 = x2 - 4;
        if (x0 >= 0 && x0 < W_)         v.x = row[x0];
        if (x0 + 1 >= 0 && x0 + 1 < W_) v.y = row[x0 + 1];
    }
    reinterpret_cast<float2*>(g_second_pad)[i] = v;
}

__global__ __launch_bounds__(288, 2)
void corr81_kernel(const float* __restrict__ first,
                   float* __restrict__ out) {
    const int h   = blockIdx.x;        // 0..111
    const int b   = blockIdx.y;        // 0..7
    const int tid = threadIdx.x;       // 0..287
    const int pp  = tid % 96;          // pixel-pair
    const int g   = tid / 96;          // dy group (dy = g*3 + i)
    const int w0  = 2 * pp;

    // e[i][m]: (pix0@dx=2m, pix1@dx=2m)
    // a[i][m]: (pix1@dx=2m-1, pix0@dx=2m+1)   via swapped first operand
    ull e[3][5], a[3][5];
#pragma unroll
    for (int i = 0; i < 3; i++)
#pragma unroll
        for (int m = 0; m < 5; m++) { e[i][m] = 0ull; a[i][m] = 0ull; }

    // padded coords: row = h + dy (dy=g*3+i), col = w0 + j for s[j]
    const float* sbase = g_second_pad +
        ((size_t)(b * C_) * HP_ + (h + g * 3)) * WP_ + w0;
    const float* fptr = first + ((size_t)(b * C_) * H_ + h) * W_ + w0;

    for (int c = 0; c < C_; c++) {
        const ull f2 = *reinterpret_cast<const ull*>(fptr);
        const ull fs = swap2(f2);
        fptr += HW_;

#pragma unroll
        for (int i = 0; i < 3; i++) {
            const float* row = sbase + i * WP_;
            const ull E0 = *reinterpret_cast<const ull*>(row);
            const ull E1 = *reinterpret_cast<const ull*>(row + 2);
            const ull E2 = *reinterpret_cast<const ull*>(row + 4);
            const ull E3 = *reinterpret_cast<const ull*>(row + 6);
            const ull E4 = *reinterpret_cast<const ull*>(row + 8);
            fma2(e[i][0], f2, E0);  fma2(a[i][0], fs, E0);
            fma2(e[i][1], f2, E1);  fma2(a[i][1], fs, E1);
            fma2(e[i][2], f2, E2);  fma2(a[i][2], fs, E2);
            fma2(e[i][3], f2, E3);  fma2(a[i][3], fs, E3);
            fma2(e[i][4], f2, E4);  fma2(a[i][4], fs, E4);
        }
        sbase += HWP_;
    }

    const unsigned sb = __float_as_uint(1.0f / (float)C_);
    const ull scale2 = (ull)sb | ((ull)sb << 32);

    // channel d = (g*3+i)*9 + dx
    float* obase = out + (((size_t)(b * 81 + g * 3 * 9)) * H_ + h) * W_ + w0;
#pragma unroll
    for (int i = 0; i < 3; i++) {
        float* od = obase + (size_t)(i * 9) * HW_;
#pragma unroll
        for (int m = 0; m < 5; m++) {          // even dx = 2m
            ull v = e[i][m]; mul2(v, scale2);
            *reinterpret_cast<ull*>(od + (size_t)(2 * m) * HW_) = v;
        }
#pragma unroll
        for (int m = 0; m < 4; m++) {          // odd dx = 2m+1
            ull v = pack_hl(a[i][m], a[i][m + 1]); mul2(v, scale2);
            *reinterpret_cast<ull*>(od + (size_t)(2 * m + 1) * HW_) = v;
        }
    }
}

extern "C" void kernel_launch(void* const* d_in, const int* in_sizes, int n_in,
                              void* d_out, int out_size) {
    const float* first  = (const float*)d_in[0];
    const float* second = (const float*)d_in[1];
    float* out = (float*)d_out;

    const int pad_elems = B_ * C_ * HWP_ / 2;            // float2 count
    pad_kernel<<<(pad_elems + 255) / 256, 256>>>(second);

    dim3 grid(H_, B_);   // (112, 8)
    corr81_kernel<<<grid, 288>>>(first, out);
}

// round 4
// speedup vs baseline: 6.1421x; 1.1835x over previous
#include <cuda_runtime.h>
#include <cstdint>

// PWC-Net correlation, B=8, C=128, H=112, W=192, 81 disps (dy,dx in [-4,4]).
// Round 4: one dy per thread-group (9 groups x 96 pixel-pair threads = 864/block)
//   -> 10 ull accs/thread (~50 regs), occupancy ~42%, full load batching.
// W-only padded second buffer; out-of-range y skips the whole channel loop
// (warp-uniform since groups are 3 whole warps).

#define B_ 8
#define C_ 128
#define H_ 112
#define W_ 192
#define HW_ (H_ * W_)
#define WP_ 200     // W + 8
#define HWP_ (H_ * WP_)

typedef unsigned long long ull;

// W-padded copy of `second`: [B, C, H, WP], 91.8 MB
__device__ float g_spad[B_ * C_ * HWP_];

__device__ __forceinline__ void fma2(ull& acc, ull a, ull b) {
    asm("fma.rn.f32x2 %0, %1, %2, %0;" : "+l"(acc) : "l"(a), "l"(b));
}
__device__ __forceinline__ void mul2(ull& v, ull s) {
    asm("mul.rn.f32x2 %0, %0, %1;" : "+l"(v) : "l"(s));
}
__device__ __forceinline__ ull pack_hl(ull a, ull b) {   // (a.hi, b.lo)
    return (a >> 32) | (b << 32);
}
__device__ __forceinline__ ull swap2(ull a) {            // (a.hi, a.lo)
    return (a >> 32) | (a << 32);
}

// one thread per padded float2: [B*C*H, 100] float2 rows
__global__ __launch_bounds__(256)
void pad_kernel(const float* __restrict__ second) {
    int i = blockIdx.x * blockDim.x + threadIdx.x;
    const int total = B_ * C_ * HWP_ / 2;
    if (i >= total) return;
    int x2  = (i % (WP_ / 2)) * 2;       // padded col: 0,2,...,198
    int row = i / (WP_ / 2);             // bc*H + y
    const float* src = second + (size_t)row * W_;
    int x0 = x2 - 4;                     // real col of .x
    float2 v;
    v.x = (x0 >= 0 && x0 < W_) ? src[x0] : 0.0f;
    v.y = (x0 + 1 >= 0 && x0 + 1 < W_) ? src[x0 + 1] : 0.0f;
    reinterpret_cast<float2*>(g_spad)[i] = v;
}

__global__ __launch_bounds__(864, 1)
void corr81_kernel(const float* __restrict__ first,
                   float* __restrict__ out) {
    const int h   = blockIdx.x;        // 0..111
    const int b   = blockIdx.y;        // 0..7
    const int tid = threadIdx.x;       // 0..863
    const int pp  = tid % 96;          // pixel-pair (3 warps per group)
    const int g   = tid / 96;          // dy index 0..8
    const int w0  = 2 * pp;

    // e[m]: (pix0@dx=2m, pix1@dx=2m)
    // a[m]: (pix1@dx=2m-1, pix0@dx=2m+1) via swapped first operand
    ull e[5], a[5];
#pragma unroll
    for (int m = 0; m < 5; m++) { e[m] = 0ull; a[m] = 0ull; }

    const int y = h + g - 4;
    if (y >= 0 && y < H_) {            // warp-uniform: whole group skips
        const float* srow = g_spad + ((size_t)(b * C_) * H_ + y) * WP_ + w0;
        const float* fptr = first  + ((size_t)(b * C_) * H_ + h) * W_ + w0;

        for (int c = 0; c < C_; c++) {
            const ull f2 = *reinterpret_cast<const ull*>(fptr);
            const ull fs = swap2(f2);
            fptr += HW_;

            const ull E0 = *reinterpret_cast<const ull*>(srow);
            const ull E1 = *reinterpret_cast<const ull*>(srow + 2);
            const ull E2 = *reinterpret_cast<const ull*>(srow + 4);
            const ull E3 = *reinterpret_cast<const ull*>(srow + 6);
            const ull E4 = *reinterpret_cast<const ull*>(srow + 8);
            srow += HWP_;

            fma2(e[0], f2, E0);  fma2(a[0], fs, E0);
            fma2(e[1], f2, E1);  fma2(a[1], fs, E1);
            fma2(e[2], f2, E2);  fma2(a[2], fs, E2);
            fma2(e[3], f2, E3);  fma2(a[3], fs, E3);
            fma2(e[4], f2, E4);  fma2(a[4], fs, E4);
        }
    }

    const unsigned sb = __float_as_uint(1.0f / (float)C_);
    const ull scale2 = (ull)sb | ((ull)sb << 32);

    // channel d = g*9 + dx
    float* od = out + (((size_t)(b * 81 + g * 9)) * H_ + h) * W_ + w0;
#pragma unroll
    for (int m = 0; m < 5; m++) {          // even dx = 2m
        ull v = e[m]; mul2(v, scale2);
        *reinterpret_cast<ull*>(od + (size_t)(2 * m) * HW_) = v;
    }
#pragma unroll
    for (int m = 0; m < 4; m++) {          // odd dx = 2m+1
        ull v = pack_hl(a[m], a[m + 1]); mul2(v, scale2);
        *reinterpret_cast<ull*>(od + (size_t)(2 * m + 1) * HW_) = v;
    }
}

extern "C" void kernel_launch(void* const* d_in, const int* in_sizes, int n_in,
                              void* d_out, int out_size) {
    const float* first  = (const float*)d_in[0];
    const float* second = (const float*)d_in[1];
    float* out = (float*)d_out;

    const int pad_elems = B_ * C_ * HWP_ / 2;            // float2 count
    pad_kernel<<<(pad_elems + 255) / 256, 256>>>(second);

    dim3 grid(H_, B_);   // (112, 8)
    corr81_kernel<<<grid, 864>>>(first, out);
}